// round 1
// baseline (speedup 1.0000x reference)
#include <cuda_runtime.h>
#include <math.h>
#include <stdint.h>

#define D_MODEL 1024
#define D_FF    4096
#define NE      8
#define CAP     4096   // max tokens per expert (worst case T=4096 all to one expert)

// ---------------- scratch (device globals: no allocation allowed) ----------------
__device__ int   g_counts[NE];
__device__ float g_sumprobs[NE];
__device__ int   g_tokidx[NE * CAP];
__device__ float g_tokw[NE * CAP];
// hidden activations: [NE][CAP][D_FF] fp32 = 512 MB
__device__ float g_h[(size_t)NE * CAP * D_FF];

// ---------------- small zero kernel (runs each replay) ----------------
__global__ void zero_small_kernel() {
    int t = threadIdx.x;
    if (t < NE) { g_counts[t] = 0; g_sumprobs[t] = 0.0f; }
}

// ---------------- router: logits -> softmax -> top2 -> lists ----------------
// 128 threads/block, 1 warp per token.
__global__ void router_kernel(const float* __restrict__ x,
                              const float* __restrict__ rw,
                              const float* __restrict__ rb,
                              int T) {
    __shared__ float s_rw[NE * D_MODEL];   // transposed: [e][k], 32 KB
    for (int i = threadIdx.x; i < D_MODEL * NE; i += blockDim.x) {
        int k = i / NE, e = i % NE;
        s_rw[e * D_MODEL + k] = rw[i];
    }
    __syncthreads();

    int warp = threadIdx.x >> 5;
    int lane = threadIdx.x & 31;
    int tok = blockIdx.x * (blockDim.x >> 5) + warp;
    if (tok >= T) return;

    const float* xr = x + (size_t)tok * D_MODEL;
    float acc[NE];
#pragma unroll
    for (int e = 0; e < NE; e++) acc[e] = 0.0f;

    for (int k = lane; k < D_MODEL; k += 32) {
        float xv = xr[k];
#pragma unroll
        for (int e = 0; e < NE; e++) acc[e] += xv * s_rw[e * D_MODEL + k];
    }
#pragma unroll
    for (int e = 0; e < NE; e++) {
#pragma unroll
        for (int off = 16; off > 0; off >>= 1)
            acc[e] += __shfl_xor_sync(0xFFFFFFFFu, acc[e], off);
    }

    if (lane == 0) {
        float logit[NE];
        float m = -1e30f;
#pragma unroll
        for (int e = 0; e < NE; e++) { logit[e] = acc[e] + rb[e]; m = fmaxf(m, logit[e]); }
        float p[NE]; float s = 0.0f;
#pragma unroll
        for (int e = 0; e < NE; e++) { p[e] = __expf(logit[e] - m); s += p[e]; }
        float inv = 1.0f / s;
#pragma unroll
        for (int e = 0; e < NE; e++) p[e] *= inv;

#pragma unroll
        for (int e = 0; e < NE; e++) atomicAdd(&g_sumprobs[e], p[e]);

        // top-2 (first occurrence on ties, like lax.top_k)
        int i1 = 0; float v1 = p[0];
#pragma unroll
        for (int e = 1; e < NE; e++) if (p[e] > v1) { v1 = p[e]; i1 = e; }
        int i2 = -1; float v2 = -1.0f;
#pragma unroll
        for (int e = 0; e < NE; e++) if (e != i1 && p[e] > v2) { v2 = p[e]; i2 = e; }

        float wn = 1.0f / (v1 + v2);
        float w1n = v1 * wn, w2n = v2 * wn;

        int s1 = atomicAdd(&g_counts[i1], 1);
        g_tokidx[i1 * CAP + s1] = tok;
        g_tokw[i1 * CAP + s1] = w1n;
        int s2 = atomicAdd(&g_counts[i2], 1);
        g_tokidx[i2 * CAP + s2] = tok;
        g_tokw[i2 * CAP + s2] = w2n;
    }
}

// ---------------- grouped GEMM1 + GELU: h = gelu(X_e @ w1[e] + b1[e]) ----------------
// 128x128 tile, BK=8, 256 threads, 8x8 per thread.
__global__ __launch_bounds__(256, 2)
void ffn1_kernel(const float* __restrict__ x,
                 const float* __restrict__ w1,
                 const float* __restrict__ b1) {
    int e = blockIdx.z;
    int count = g_counts[e];
    int row0 = blockIdx.y * 128;
    if (row0 >= count) return;
    int col0 = blockIdx.x * 128;

    __shared__ float As[8][128];
    __shared__ float Bs[8][128];

    int tid = threadIdx.x;
    int tx = tid & 15;        // n-dir
    int ty = tid >> 4;        // m-dir

    // A loader: 128 rows x 8 k, float4 each -> thread loads row tid/2, k-offset (tid&1)*4
    int arow = tid >> 1;
    int acol = (tid & 1) * 4;
    int grow = row0 + arow;
    int tokA = g_tokidx[e * CAP + (grow < count ? grow : count - 1)];
    const float* aptr = x + (size_t)tokA * D_MODEL + acol;

    // B loader: 8 rows x 128 cols, float4 -> row tid/32, col (tid&31)*4
    int brow = tid >> 5;
    int bcol = (tid & 31) * 4;
    const float* bptr = w1 + (size_t)e * D_MODEL * D_FF + (size_t)brow * D_FF + col0 + bcol;

    float accr[8][8];
#pragma unroll
    for (int i = 0; i < 8; i++)
#pragma unroll
        for (int j = 0; j < 8; j++) accr[i][j] = 0.0f;

    for (int kt = 0; kt < D_MODEL; kt += 8) {
        float4 av = *(const float4*)(aptr + kt);
        As[acol + 0][arow] = av.x;
        As[acol + 1][arow] = av.y;
        As[acol + 2][arow] = av.z;
        As[acol + 3][arow] = av.w;
        float4 bv = *(const float4*)(bptr + (size_t)kt * D_FF);
        *(float4*)&Bs[brow][bcol] = bv;
        __syncthreads();
#pragma unroll
        for (int k = 0; k < 8; k++) {
            float a[8], b[8];
            *(float4*)(a)     = *(const float4*)&As[k][ty * 8];
            *(float4*)(a + 4) = *(const float4*)&As[k][ty * 8 + 4];
            *(float4*)(b)     = *(const float4*)&Bs[k][tx * 8];
            *(float4*)(b + 4) = *(const float4*)&Bs[k][tx * 8 + 4];
#pragma unroll
            for (int i = 0; i < 8; i++)
#pragma unroll
                for (int j = 0; j < 8; j++) accr[i][j] += a[i] * b[j];
        }
        __syncthreads();
    }

    // epilogue: + b1, exact gelu, store valid rows
#pragma unroll
    for (int i = 0; i < 8; i++) {
        int m = ty * 8 + i;
        int gr = row0 + m;
        if (gr >= count) continue;
        float* hrow = &g_h[((size_t)e * CAP + gr) * D_FF + col0];
#pragma unroll
        for (int j = 0; j < 8; j++) {
            int n = tx * 8 + j;
            float v = accr[i][j] + b1[e * D_FF + col0 + n];
            float g = 0.5f * v * (1.0f + erff(v * 0.70710678118654752f));
            hrow[n] = g;
        }
    }
}

// ---------------- grouped GEMM2 + weighted scatter: out += w * (h @ w2[e] + b2[e]) ----------------
__global__ __launch_bounds__(256, 2)
void ffn2_kernel(const float* __restrict__ w2,
                 const float* __restrict__ b2,
                 float* __restrict__ out) {
    int e = blockIdx.z;
    int count = g_counts[e];
    int row0 = blockIdx.y * 128;
    if (row0 >= count) return;
    int col0 = blockIdx.x * 128;

    __shared__ float As[8][128];
    __shared__ float Bs[8][128];

    int tid = threadIdx.x;
    int tx = tid & 15;
    int ty = tid >> 4;

    int arow = tid >> 1;
    int acol = (tid & 1) * 4;
    const float* aptr = &g_h[((size_t)e * CAP + row0 + arow) * D_FF + acol];

    int brow = tid >> 5;
    int bcol = (tid & 31) * 4;
    const float* bptr = w2 + (size_t)e * D_FF * D_MODEL + (size_t)brow * D_MODEL + col0 + bcol;

    float accr[8][8];
#pragma unroll
    for (int i = 0; i < 8; i++)
#pragma unroll
        for (int j = 0; j < 8; j++) accr[i][j] = 0.0f;

    for (int kt = 0; kt < D_FF; kt += 8) {
        float4 av = *(const float4*)(aptr + kt);
        As[acol + 0][arow] = av.x;
        As[acol + 1][arow] = av.y;
        As[acol + 2][arow] = av.z;
        As[acol + 3][arow] = av.w;
        float4 bv = *(const float4*)(bptr + (size_t)kt * D_MODEL);
        *(float4*)&Bs[brow][bcol] = bv;
        __syncthreads();
#pragma unroll
        for (int k = 0; k < 8; k++) {
            float a[8], b[8];
            *(float4*)(a)     = *(const float4*)&As[k][ty * 8];
            *(float4*)(a + 4) = *(const float4*)&As[k][ty * 8 + 4];
            *(float4*)(b)     = *(const float4*)&Bs[k][tx * 8];
            *(float4*)(b + 4) = *(const float4*)&Bs[k][tx * 8 + 4];
#pragma unroll
            for (int i = 0; i < 8; i++)
#pragma unroll
                for (int j = 0; j < 8; j++) accr[i][j] += a[i] * b[j];
        }
        __syncthreads();
    }

#pragma unroll
    for (int i = 0; i < 8; i++) {
        int m = ty * 8 + i;
        int gr = row0 + m;
        if (gr >= count) continue;
        int tok = g_tokidx[e * CAP + gr];
        float w = g_tokw[e * CAP + gr];
        float* orow = out + (size_t)tok * D_MODEL + col0;
#pragma unroll
        for (int j = 0; j < 8; j++) {
            int n = tx * 8 + j;
            float v = accr[i][j] + b2[e * D_MODEL + col0 + n];
            atomicAdd(&orow[n], w * v);
        }
    }
}

// ---------------- aux loss: var(mean_probs, ddof=1) ----------------
__global__ void aux_kernel(float* out_aux, float invT) {
    if (threadIdx.x == 0 && blockIdx.x == 0) {
        float m[NE]; float mu = 0.0f;
#pragma unroll
        for (int e = 0; e < NE; e++) { m[e] = g_sumprobs[e] * invT; mu += m[e]; }
        mu *= (1.0f / NE);
        float v = 0.0f;
#pragma unroll
        for (int e = 0; e < NE; e++) { float d = m[e] - mu; v += d * d; }
        *out_aux = v / (NE - 1);
    }
}

// ---------------- launch ----------------
extern "C" void kernel_launch(void* const* d_in, const int* in_sizes, int n_in,
                              void* d_out, int out_size) {
    const float* x  = (const float*)d_in[0];
    const float* rw = (const float*)d_in[1];
    const float* rb = (const float*)d_in[2];
    const float* w1 = (const float*)d_in[3];
    const float* b1 = (const float*)d_in[4];
    const float* w2 = (const float*)d_in[5];
    const float* b2 = (const float*)d_in[6];
    float* out = (float*)d_out;

    int T = in_sizes[0] / D_MODEL;   // tokens (4096 for the given shapes)

    cudaMemsetAsync(d_out, 0, (size_t)T * D_MODEL * sizeof(float));
    zero_small_kernel<<<1, 32>>>();
    router_kernel<<<(T + 3) / 4, 128>>>(x, rw, rb, T);

    dim3 g1(D_FF / 128, (T + 127) / 128, NE);
    ffn1_kernel<<<g1, 256>>>(x, w1, b1);

    dim3 g2(D_MODEL / 128, (T + 127) / 128, NE);
    ffn2_kernel<<<g2, 256>>>(w2, b2, out);

    if (out_size > T * D_MODEL) {
        aux_kernel<<<1, 32>>>(out + (size_t)T * D_MODEL, 1.0f / (float)T);
    }
}

// round 2
// speedup vs baseline: 2.0147x; 2.0147x over previous
#include <cuda_runtime.h>
#include <math.h>
#include <stdint.h>

#define D_MODEL 1024
#define D_FF    4096
#define NE      8
#define CAP     4096

// ---------------- scratch ----------------
__device__ int   g_counts[NE];
__device__ float g_sumprobs[NE];
__device__ int   g_tokidx[NE * CAP];
__device__ float g_tokw[NE * CAP];
__device__ float g_h[(size_t)NE * CAP * D_FF];   // 512 MB

__global__ void zero_small_kernel() {
    int t = threadIdx.x;
    if (t < NE) { g_counts[t] = 0; g_sumprobs[t] = 0.0f; }
}

// ---------------- router ----------------
__global__ void router_kernel(const float* __restrict__ x,
                              const float* __restrict__ rw,
                              const float* __restrict__ rb,
                              int T) {
    __shared__ float s_rw[NE * D_MODEL];
    for (int i = threadIdx.x; i < D_MODEL * NE; i += blockDim.x) {
        int k = i / NE, e = i % NE;
        s_rw[e * D_MODEL + k] = rw[i];
    }
    __syncthreads();

    int warp = threadIdx.x >> 5;
    int lane = threadIdx.x & 31;
    int tok = blockIdx.x * (blockDim.x >> 5) + warp;
    if (tok >= T) return;

    const float* xr = x + (size_t)tok * D_MODEL;
    float acc[NE];
#pragma unroll
    for (int e = 0; e < NE; e++) acc[e] = 0.0f;
    for (int k = lane; k < D_MODEL; k += 32) {
        float xv = xr[k];
#pragma unroll
        for (int e = 0; e < NE; e++) acc[e] += xv * s_rw[e * D_MODEL + k];
    }
#pragma unroll
    for (int e = 0; e < NE; e++) {
#pragma unroll
        for (int off = 16; off > 0; off >>= 1)
            acc[e] += __shfl_xor_sync(0xFFFFFFFFu, acc[e], off);
    }

    if (lane == 0) {
        float logit[NE]; float m = -1e30f;
#pragma unroll
        for (int e = 0; e < NE; e++) { logit[e] = acc[e] + rb[e]; m = fmaxf(m, logit[e]); }
        float p[NE]; float s = 0.0f;
#pragma unroll
        for (int e = 0; e < NE; e++) { p[e] = __expf(logit[e] - m); s += p[e]; }
        float inv = 1.0f / s;
#pragma unroll
        for (int e = 0; e < NE; e++) p[e] *= inv;
#pragma unroll
        for (int e = 0; e < NE; e++) atomicAdd(&g_sumprobs[e], p[e]);

        int i1 = 0; float v1 = p[0];
#pragma unroll
        for (int e = 1; e < NE; e++) if (p[e] > v1) { v1 = p[e]; i1 = e; }
        int i2 = -1; float v2 = -1.0f;
#pragma unroll
        for (int e = 0; e < NE; e++) if (e != i1 && p[e] > v2) { v2 = p[e]; i2 = e; }

        float wn = 1.0f / (v1 + v2);
        int s1 = atomicAdd(&g_counts[i1], 1);
        g_tokidx[i1 * CAP + s1] = tok;  g_tokw[i1 * CAP + s1] = v1 * wn;
        int s2 = atomicAdd(&g_counts[i2], 1);
        g_tokidx[i2 * CAP + s2] = tok;  g_tokw[i2 * CAP + s2] = v2 * wn;
    }
}

// ---------------- tf32 helpers ----------------
__device__ __forceinline__ unsigned f2tf(float f) {
    unsigned u;
    asm("cvt.rna.tf32.f32 %0, %1;" : "=r"(u) : "f"(f));
    return u;
}

__device__ __forceinline__ void mma_tf32(float c[4],
                                         unsigned a0, unsigned a1, unsigned a2, unsigned a3,
                                         unsigned b0, unsigned b1) {
    asm volatile(
        "mma.sync.aligned.m16n8k8.row.col.f32.tf32.tf32.f32 "
        "{%0,%1,%2,%3}, {%4,%5,%6,%7}, {%8,%9}, {%0,%1,%2,%3};\n"
        : "+f"(c[0]), "+f"(c[1]), "+f"(c[2]), "+f"(c[3])
        : "r"(a0), "r"(a1), "r"(a2), "r"(a3), "r"(b0), "r"(b1));
}

// smem strides (in 32-bit words), padded for conflict-free fragment loads
#define ASTRIDE 20    // BK(16)+4
#define BSTRIDE 136   // BN(128)+8

// ---------------- FFN1: h = gelu(X_e @ w1[e] + b1[e]) ----------------
__global__ __launch_bounds__(256, 1)
void ffn1_kernel(const float* __restrict__ x,
                 const float* __restrict__ w1,
                 const float* __restrict__ b1) {
    int e = blockIdx.z;
    int count = g_counts[e];
    int row0 = blockIdx.y * 128;
    if (row0 >= count) return;
    int col0 = blockIdx.x * 128;

    __shared__ unsigned As[2][128 * ASTRIDE];
    __shared__ unsigned Bs[2][16 * BSTRIDE];
    __shared__ int s_tok[128];

    int t = threadIdx.x;
    if (t < 128) {
        int gr = row0 + t;
        s_tok[t] = g_tokidx[e * CAP + (gr < count ? gr : count - 1)];
    }
    __syncthreads();

    int lane = t & 31, wid = t >> 5;
    int warp_m = wid >> 2, warp_n = wid & 3;
    int gid = lane >> 2, tig = lane & 3;

    // staging coords
    int a0row = t >> 2,            a0c = (t & 3) * 4;          // ids 0..255
    int a1row = (t + 256) >> 2,    a1c = a0c;                  // ids 256..511
    int b0row = t >> 5,            b0c = (t & 31) * 4;
    int b1row = (t + 256) >> 5,    b1c = b0c;

    const float* w1e = w1 + (size_t)e * D_MODEL * D_FF + col0;

    float acc[4][4][4];
#pragma unroll
    for (int i = 0; i < 4; i++)
#pragma unroll
        for (int j = 0; j < 4; j++)
#pragma unroll
            for (int q = 0; q < 4; q++) acc[i][j][q] = 0.0f;

    // prologue: stage tile 0
    {
        float4 va0 = *(const float4*)(x + (size_t)s_tok[a0row] * D_MODEL + a0c);
        float4 va1 = *(const float4*)(x + (size_t)s_tok[a1row] * D_MODEL + a1c);
        float4 vb0 = *(const float4*)(w1e + (size_t)b0row * D_FF + b0c);
        float4 vb1 = *(const float4*)(w1e + (size_t)b1row * D_FF + b1c);
        unsigned* A = As[0]; unsigned* B = Bs[0];
        A[a0row*ASTRIDE+a0c+0]=f2tf(va0.x); A[a0row*ASTRIDE+a0c+1]=f2tf(va0.y);
        A[a0row*ASTRIDE+a0c+2]=f2tf(va0.z); A[a0row*ASTRIDE+a0c+3]=f2tf(va0.w);
        A[a1row*ASTRIDE+a1c+0]=f2tf(va1.x); A[a1row*ASTRIDE+a1c+1]=f2tf(va1.y);
        A[a1row*ASTRIDE+a1c+2]=f2tf(va1.z); A[a1row*ASTRIDE+a1c+3]=f2tf(va1.w);
        B[b0row*BSTRIDE+b0c+0]=f2tf(vb0.x); B[b0row*BSTRIDE+b0c+1]=f2tf(vb0.y);
        B[b0row*BSTRIDE+b0c+2]=f2tf(vb0.z); B[b0row*BSTRIDE+b0c+3]=f2tf(vb0.w);
        B[b1row*BSTRIDE+b1c+0]=f2tf(vb1.x); B[b1row*BSTRIDE+b1c+1]=f2tf(vb1.y);
        B[b1row*BSTRIDE+b1c+2]=f2tf(vb1.z); B[b1row*BSTRIDE+b1c+3]=f2tf(vb1.w);
    }
    __syncthreads();

    const int NITER = D_MODEL / 16;
    for (int it = 0; it < NITER; it++) {
        int buf = it & 1;
        float4 va0, va1, vb0, vb1;
        bool more = (it + 1 < NITER);
        if (more) {
            int kt = (it + 1) * 16;
            va0 = *(const float4*)(x + (size_t)s_tok[a0row] * D_MODEL + kt + a0c);
            va1 = *(const float4*)(x + (size_t)s_tok[a1row] * D_MODEL + kt + a1c);
            vb0 = *(const float4*)(w1e + (size_t)(kt + b0row) * D_FF + b0c);
            vb1 = *(const float4*)(w1e + (size_t)(kt + b1row) * D_FF + b1c);
        }

        const unsigned* A = As[buf]; const unsigned* B = Bs[buf];
#pragma unroll
        for (int ks = 0; ks < 16; ks += 8) {
            unsigned af[4][4], bf[4][2];
#pragma unroll
            for (int i = 0; i < 4; i++) {
                int m = warp_m * 64 + i * 16;
                af[i][0] = A[(m + gid)     * ASTRIDE + ks + tig];
                af[i][1] = A[(m + gid + 8) * ASTRIDE + ks + tig];
                af[i][2] = A[(m + gid)     * ASTRIDE + ks + tig + 4];
                af[i][3] = A[(m + gid + 8) * ASTRIDE + ks + tig + 4];
            }
#pragma unroll
            for (int j = 0; j < 4; j++) {
                int n = warp_n * 32 + j * 8;
                bf[j][0] = B[(ks + tig)     * BSTRIDE + n + gid];
                bf[j][1] = B[(ks + tig + 4) * BSTRIDE + n + gid];
            }
#pragma unroll
            for (int i = 0; i < 4; i++)
#pragma unroll
                for (int j = 0; j < 4; j++)
                    mma_tf32(acc[i][j], af[i][0], af[i][1], af[i][2], af[i][3],
                             bf[j][0], bf[j][1]);
        }

        if (more) {
            unsigned* An = As[buf ^ 1]; unsigned* Bn = Bs[buf ^ 1];
            An[a0row*ASTRIDE+a0c+0]=f2tf(va0.x); An[a0row*ASTRIDE+a0c+1]=f2tf(va0.y);
            An[a0row*ASTRIDE+a0c+2]=f2tf(va0.z); An[a0row*ASTRIDE+a0c+3]=f2tf(va0.w);
            An[a1row*ASTRIDE+a1c+0]=f2tf(va1.x); An[a1row*ASTRIDE+a1c+1]=f2tf(va1.y);
            An[a1row*ASTRIDE+a1c+2]=f2tf(va1.z); An[a1row*ASTRIDE+a1c+3]=f2tf(va1.w);
            Bn[b0row*BSTRIDE+b0c+0]=f2tf(vb0.x); Bn[b0row*BSTRIDE+b0c+1]=f2tf(vb0.y);
            Bn[b0row*BSTRIDE+b0c+2]=f2tf(vb0.z); Bn[b0row*BSTRIDE+b0c+3]=f2tf(vb0.w);
            Bn[b1row*BSTRIDE+b1c+0]=f2tf(vb1.x); Bn[b1row*BSTRIDE+b1c+1]=f2tf(vb1.y);
            Bn[b1row*BSTRIDE+b1c+2]=f2tf(vb1.z); Bn[b1row*BSTRIDE+b1c+3]=f2tf(vb1.w);
        }
        __syncthreads();
    }

    // epilogue: + b1, exact gelu, store valid rows
#pragma unroll
    for (int i = 0; i < 4; i++) {
        int mrow = warp_m * 64 + i * 16 + gid;
#pragma unroll
        for (int half = 0; half < 2; half++) {
            int gr = row0 + mrow + half * 8;
            if (gr >= count) continue;
            float* hrow = &g_h[((size_t)e * CAP + gr) * D_FF + col0];
#pragma unroll
            for (int j = 0; j < 4; j++) {
                int c = warp_n * 32 + j * 8 + tig * 2;
                float v0 = acc[i][j][half * 2 + 0] + b1[e * D_FF + col0 + c];
                float v1 = acc[i][j][half * 2 + 1] + b1[e * D_FF + col0 + c + 1];
                float g0 = 0.5f * v0 * (1.0f + erff(v0 * 0.70710678118654752f));
                float g1 = 0.5f * v1 * (1.0f + erff(v1 * 0.70710678118654752f));
                *(float2*)(hrow + c) = make_float2(g0, g1);
            }
        }
    }
}

// ---------------- FFN2: out += w * (h @ w2[e] + b2[e]) ----------------
__global__ __launch_bounds__(256, 1)
void ffn2_kernel(const float* __restrict__ w2,
                 const float* __restrict__ b2,
                 float* __restrict__ out) {
    int e = blockIdx.z;
    int count = g_counts[e];
    int row0 = blockIdx.y * 128;
    if (row0 >= count) return;
    int col0 = blockIdx.x * 128;

    __shared__ unsigned As[2][128 * ASTRIDE];
    __shared__ unsigned Bs[2][16 * BSTRIDE];

    int t = threadIdx.x;
    int lane = t & 31, wid = t >> 5;
    int warp_m = wid >> 2, warp_n = wid & 3;
    int gid = lane >> 2, tig = lane & 3;

    int a0row = t >> 2,         a0c = (t & 3) * 4;
    int a1row = (t + 256) >> 2, a1c = a0c;
    int b0row = t >> 5,         b0c = (t & 31) * 4;
    int b1row = (t + 256) >> 5, b1c = b0c;

    const float* he  = g_h + ((size_t)e * CAP + row0) * D_FF;
    const float* w2e = w2 + (size_t)e * D_FF * D_MODEL + col0;

    float acc[4][4][4];
#pragma unroll
    for (int i = 0; i < 4; i++)
#pragma unroll
        for (int j = 0; j < 4; j++)
#pragma unroll
            for (int q = 0; q < 4; q++) acc[i][j][q] = 0.0f;

    {
        float4 va0 = *(const float4*)(he + (size_t)a0row * D_FF + a0c);
        float4 va1 = *(const float4*)(he + (size_t)a1row * D_FF + a1c);
        float4 vb0 = *(const float4*)(w2e + (size_t)b0row * D_MODEL + b0c);
        float4 vb1 = *(const float4*)(w2e + (size_t)b1row * D_MODEL + b1c);
        unsigned* A = As[0]; unsigned* B = Bs[0];
        A[a0row*ASTRIDE+a0c+0]=f2tf(va0.x); A[a0row*ASTRIDE+a0c+1]=f2tf(va0.y);
        A[a0row*ASTRIDE+a0c+2]=f2tf(va0.z); A[a0row*ASTRIDE+a0c+3]=f2tf(va0.w);
        A[a1row*ASTRIDE+a1c+0]=f2tf(va1.x); A[a1row*ASTRIDE+a1c+1]=f2tf(va1.y);
        A[a1row*ASTRIDE+a1c+2]=f2tf(va1.z); A[a1row*ASTRIDE+a1c+3]=f2tf(va1.w);
        B[b0row*BSTRIDE+b0c+0]=f2tf(vb0.x); B[b0row*BSTRIDE+b0c+1]=f2tf(vb0.y);
        B[b0row*BSTRIDE+b0c+2]=f2tf(vb0.z); B[b0row*BSTRIDE+b0c+3]=f2tf(vb0.w);
        B[b1row*BSTRIDE+b1c+0]=f2tf(vb1.x); B[b1row*BSTRIDE+b1c+1]=f2tf(vb1.y);
        B[b1row*BSTRIDE+b1c+2]=f2tf(vb1.z); B[b1row*BSTRIDE+b1c+3]=f2tf(vb1.w);
    }
    __syncthreads();

    const int NITER = D_FF / 16;
    for (int it = 0; it < NITER; it++) {
        int buf = it & 1;
        float4 va0, va1, vb0, vb1;
        bool more = (it + 1 < NITER);
        if (more) {
            int kt = (it + 1) * 16;
            va0 = *(const float4*)(he + (size_t)a0row * D_FF + kt + a0c);
            va1 = *(const float4*)(he + (size_t)a1row * D_FF + kt + a1c);
            vb0 = *(const float4*)(w2e + (size_t)(kt + b0row) * D_MODEL + b0c);
            vb1 = *(const float4*)(w2e + (size_t)(kt + b1row) * D_MODEL + b1c);
        }

        const unsigned* A = As[buf]; const unsigned* B = Bs[buf];
#pragma unroll
        for (int ks = 0; ks < 16; ks += 8) {
            unsigned af[4][4], bf[4][2];
#pragma unroll
            for (int i = 0; i < 4; i++) {
                int m = warp_m * 64 + i * 16;
                af[i][0] = A[(m + gid)     * ASTRIDE + ks + tig];
                af[i][1] = A[(m + gid + 8) * ASTRIDE + ks + tig];
                af[i][2] = A[(m + gid)     * ASTRIDE + ks + tig + 4];
                af[i][3] = A[(m + gid + 8) * ASTRIDE + ks + tig + 4];
            }
#pragma unroll
            for (int j = 0; j < 4; j++) {
                int n = warp_n * 32 + j * 8;
                bf[j][0] = B[(ks + tig)     * BSTRIDE + n + gid];
                bf[j][1] = B[(ks + tig + 4) * BSTRIDE + n + gid];
            }
#pragma unroll
            for (int i = 0; i < 4; i++)
#pragma unroll
                for (int j = 0; j < 4; j++)
                    mma_tf32(acc[i][j], af[i][0], af[i][1], af[i][2], af[i][3],
                             bf[j][0], bf[j][1]);
        }

        if (more) {
            unsigned* An = As[buf ^ 1]; unsigned* Bn = Bs[buf ^ 1];
            An[a0row*ASTRIDE+a0c+0]=f2tf(va0.x); An[a0row*ASTRIDE+a0c+1]=f2tf(va0.y);
            An[a0row*ASTRIDE+a0c+2]=f2tf(va0.z); An[a0row*ASTRIDE+a0c+3]=f2tf(va0.w);
            An[a1row*ASTRIDE+a1c+0]=f2tf(va1.x); An[a1row*ASTRIDE+a1c+1]=f2tf(va1.y);
            An[a1row*ASTRIDE+a1c+2]=f2tf(va1.z); An[a1row*ASTRIDE+a1c+3]=f2tf(va1.w);
            Bn[b0row*BSTRIDE+b0c+0]=f2tf(vb0.x); Bn[b0row*BSTRIDE+b0c+1]=f2tf(vb0.y);
            Bn[b0row*BSTRIDE+b0c+2]=f2tf(vb0.z); Bn[b0row*BSTRIDE+b0c+3]=f2tf(vb0.w);
            Bn[b1row*BSTRIDE+b1c+0]=f2tf(vb1.x); Bn[b1row*BSTRIDE+b1c+1]=f2tf(vb1.y);
            Bn[b1row*BSTRIDE+b1c+2]=f2tf(vb1.z); Bn[b1row*BSTRIDE+b1c+3]=f2tf(vb1.w);
        }
        __syncthreads();
    }

    // epilogue: weighted atomic scatter
#pragma unroll
    for (int i = 0; i < 4; i++) {
        int mrow = warp_m * 64 + i * 16 + gid;
#pragma unroll
        for (int half = 0; half < 2; half++) {
            int gr = row0 + mrow + half * 8;
            if (gr >= count) continue;
            int tok = g_tokidx[e * CAP + gr];
            float w  = g_tokw[e * CAP + gr];
            float* orow = out + (size_t)tok * D_MODEL + col0;
#pragma unroll
            for (int j = 0; j < 4; j++) {
                int c = warp_n * 32 + j * 8 + tig * 2;
                float v0 = acc[i][j][half * 2 + 0] + b2[e * D_MODEL + col0 + c];
                float v1 = acc[i][j][half * 2 + 1] + b2[e * D_MODEL + col0 + c + 1];
                atomicAdd(&orow[c],     w * v0);
                atomicAdd(&orow[c + 1], w * v1);
            }
        }
    }
}

// ---------------- aux loss ----------------
__global__ void aux_kernel(float* out_aux, float invT) {
    if (threadIdx.x == 0 && blockIdx.x == 0) {
        float m[NE]; float mu = 0.0f;
#pragma unroll
        for (int e = 0; e < NE; e++) { m[e] = g_sumprobs[e] * invT; mu += m[e]; }
        mu *= (1.0f / NE);
        float v = 0.0f;
#pragma unroll
        for (int e = 0; e < NE; e++) { float d = m[e] - mu; v += d * d; }
        *out_aux = v / (NE - 1);
    }
}

// ---------------- launch ----------------
extern "C" void kernel_launch(void* const* d_in, const int* in_sizes, int n_in,
                              void* d_out, int out_size) {
    const float* x  = (const float*)d_in[0];
    const float* rw = (const float*)d_in[1];
    const float* rb = (const float*)d_in[2];
    const float* w1 = (const float*)d_in[3];
    const float* b1 = (const float*)d_in[4];
    const float* w2 = (const float*)d_in[5];
    const float* b2 = (const float*)d_in[6];
    float* out = (float*)d_out;

    int T = in_sizes[0] / D_MODEL;

    cudaMemsetAsync(d_out, 0, (size_t)T * D_MODEL * sizeof(float));
    zero_small_kernel<<<1, 32>>>();
    router_kernel<<<(T + 3) / 4, 128>>>(x, rw, rb, T);

    dim3 g1(D_FF / 128, CAP / 128, NE);
    ffn1_kernel<<<g1, 256>>>(x, w1, b1);

    dim3 g2(D_MODEL / 128, CAP / 128, NE);
    ffn2_kernel<<<g2, 256>>>(w2, b2, out);

    if (out_size > T * D_MODEL) {
        aux_kernel<<<1, 32>>>(out + (size_t)T * D_MODEL, 1.0f / (float)T);
    }
}

// round 7
// speedup vs baseline: 2.8780x; 1.4285x over previous
#include <cuda_runtime.h>
#include <math.h>
#include <stdint.h>

#define D_MODEL 1024
#define D_FF    4096
#define NE      8
#define CAP     4096

// ---------------- device scratch ----------------
__device__ int      g_counts[NE];
__device__ float    g_sumprobs[NE];
__device__ int      g_tokidx[NE * CAP];
__device__ float    g_tokw[NE * CAP];
__device__ unsigned g_xt[(size_t)CAP * D_MODEL];           // tf32 tokens
__device__ unsigned g_w1c[(size_t)NE * D_MODEL * D_FF];    // tf32 w1 [e][k][n]
__device__ unsigned g_w2c[(size_t)NE * D_FF * D_MODEL];    // tf32 w2 [e][k][n]
__device__ unsigned g_h[(size_t)NE * CAP * D_FF];          // tf32 hidden

__global__ void zero_small_kernel() {
    int t = threadIdx.x;
    if (t < NE) { g_counts[t] = 0; g_sumprobs[t] = 0.0f; }
}

// ---------------- helpers ----------------
__device__ __forceinline__ unsigned f2tf(float f) {
    unsigned u;
    asm("cvt.rna.tf32.f32 %0, %1;" : "=r"(u) : "f"(f));
    return u;
}

__device__ __forceinline__ void mma_tf32(float c[4],
                                         unsigned a0, unsigned a1, unsigned a2, unsigned a3,
                                         unsigned b0, unsigned b1) {
    asm volatile(
        "mma.sync.aligned.m16n8k8.row.col.f32.tf32.tf32.f32 "
        "{%0,%1,%2,%3}, {%4,%5,%6,%7}, {%8,%9}, {%0,%1,%2,%3};\n"
        : "+f"(c[0]), "+f"(c[1]), "+f"(c[2]), "+f"(c[3])
        : "r"(a0), "r"(a1), "r"(a2), "r"(a3), "r"(b0), "r"(b1));
}

#define ASTRIDE 20    // BK(16)+4
#define BSTRIDE 136   // BN(128)+8

// ---------------- tf32 pre-conversion ----------------
// NOTE: destination arrays are referenced INSIDE device code (never passed as
// kernel args from host — a __device__ symbol in host code is the host shadow).
__device__ __forceinline__ void conv_body(const float* __restrict__ in,
                                          unsigned* __restrict__ out, size_t n4) {
    size_t i = (size_t)blockIdx.x * blockDim.x + threadIdx.x;
    size_t stride = (size_t)gridDim.x * blockDim.x;
    for (; i < n4; i += stride) {
        float4 v = ((const float4*)in)[i];
        uint4 o;
        o.x = f2tf(v.x); o.y = f2tf(v.y); o.z = f2tf(v.z); o.w = f2tf(v.w);
        ((uint4*)out)[i] = o;
    }
}

__global__ void convx_kernel(const float* __restrict__ in, size_t n4) {
    conv_body(in, g_xt, n4);
}
__global__ void convw1_kernel(const float* __restrict__ in, size_t n4) {
    conv_body(in, g_w1c, n4);
}
__global__ void convw2_kernel(const float* __restrict__ in, size_t n4) {
    conv_body(in, g_w2c, n4);
}

// ---------------- router ----------------
__global__ void router_kernel(const float* __restrict__ x,
                              const float* __restrict__ rw,
                              const float* __restrict__ rb,
                              int T) {
    __shared__ float s_rw[NE * D_MODEL];
    for (int i = threadIdx.x; i < D_MODEL * NE; i += blockDim.x) {
        int k = i / NE, e = i % NE;
        s_rw[e * D_MODEL + k] = rw[i];
    }
    __syncthreads();

    int warp = threadIdx.x >> 5;
    int lane = threadIdx.x & 31;
    int tok = blockIdx.x * (blockDim.x >> 5) + warp;
    if (tok >= T) return;

    const float* xr = x + (size_t)tok * D_MODEL;
    float acc[NE];
#pragma unroll
    for (int e = 0; e < NE; e++) acc[e] = 0.0f;
    for (int k = lane; k < D_MODEL; k += 32) {
        float xv = xr[k];
#pragma unroll
        for (int e = 0; e < NE; e++) acc[e] += xv * s_rw[e * D_MODEL + k];
    }
#pragma unroll
    for (int e = 0; e < NE; e++) {
#pragma unroll
        for (int off = 16; off > 0; off >>= 1)
            acc[e] += __shfl_xor_sync(0xFFFFFFFFu, acc[e], off);
    }

    if (lane == 0) {
        float logit[NE]; float m = -1e30f;
#pragma unroll
        for (int e = 0; e < NE; e++) { logit[e] = acc[e] + rb[e]; m = fmaxf(m, logit[e]); }
        float p[NE]; float s = 0.0f;
#pragma unroll
        for (int e = 0; e < NE; e++) { p[e] = __expf(logit[e] - m); s += p[e]; }
        float inv = 1.0f / s;
#pragma unroll
        for (int e = 0; e < NE; e++) p[e] *= inv;
#pragma unroll
        for (int e = 0; e < NE; e++) atomicAdd(&g_sumprobs[e], p[e]);

        int i1 = 0; float v1 = p[0];
#pragma unroll
        for (int e = 1; e < NE; e++) if (p[e] > v1) { v1 = p[e]; i1 = e; }
        int i2 = -1; float v2 = -1.0f;
#pragma unroll
        for (int e = 0; e < NE; e++) if (e != i1 && p[e] > v2) { v2 = p[e]; i2 = e; }

        float wn = 1.0f / (v1 + v2);
        int s1 = atomicAdd(&g_counts[i1], 1);
        g_tokidx[i1 * CAP + s1] = tok;  g_tokw[i1 * CAP + s1] = v1 * wn;
        int s2 = atomicAdd(&g_counts[i2], 1);
        g_tokidx[i2 * CAP + s2] = tok;  g_tokw[i2 * CAP + s2] = v2 * wn;
    }
}

// ---------------- FFN1: h = tf32(gelu(X_e @ w1[e] + b1[e])) ----------------
__global__ __launch_bounds__(256, 2)
void ffn1_kernel(const float* __restrict__ b1) {
    __shared__ unsigned As[2][128 * ASTRIDE];
    __shared__ unsigned Bs[2][16 * BSTRIDE];
    __shared__ int s_tok[128];

    int e = blockIdx.z;
    int count = g_counts[e];
    int row0 = blockIdx.y * 128;
    if (row0 >= count) return;
    int col0 = blockIdx.x * 128;

    int t = threadIdx.x;
    if (t < 128) {
        int gr = row0 + t;
        s_tok[t] = g_tokidx[e * CAP + (gr < count ? gr : count - 1)];
    }
    __syncthreads();

    int lane = t & 31, wid = t >> 5;
    int warp_m = wid >> 2, warp_n = wid & 3;
    int gid = lane >> 2, tig = lane & 3;

    int a0row = t >> 2,            a0c = (t & 3) * 4;
    int a1row = (t + 256) >> 2,    a1c = a0c;
    int b0row = t >> 5,            b0c = (t & 31) * 4;
    int b1row = (t + 256) >> 5,    b1c = b0c;

    const unsigned* xr0 = g_xt + (size_t)s_tok[a0row] * D_MODEL + a0c;
    const unsigned* xr1 = g_xt + (size_t)s_tok[a1row] * D_MODEL + a1c;
    const unsigned* w1e = g_w1c + (size_t)e * D_MODEL * D_FF + col0;

    float acc[4][4][4];
#pragma unroll
    for (int i = 0; i < 4; i++)
#pragma unroll
        for (int j = 0; j < 4; j++)
#pragma unroll
            for (int q = 0; q < 4; q++) acc[i][j][q] = 0.0f;

    // prologue: stage tile 0
    {
        uint4 va0 = *(const uint4*)(xr0);
        uint4 va1 = *(const uint4*)(xr1);
        uint4 vb0 = *(const uint4*)(w1e + (size_t)b0row * D_FF + b0c);
        uint4 vb1 = *(const uint4*)(w1e + (size_t)b1row * D_FF + b1c);
        unsigned* A = As[0]; unsigned* B = Bs[0];
        A[a0row*ASTRIDE+a0c+0]=va0.x; A[a0row*ASTRIDE+a0c+1]=va0.y;
        A[a0row*ASTRIDE+a0c+2]=va0.z; A[a0row*ASTRIDE+a0c+3]=va0.w;
        A[a1row*ASTRIDE+a1c+0]=va1.x; A[a1row*ASTRIDE+a1c+1]=va1.y;
        A[a1row*ASTRIDE+a1c+2]=va1.z; A[a1row*ASTRIDE+a1c+3]=va1.w;
        B[b0row*BSTRIDE+b0c+0]=vb0.x; B[b0row*BSTRIDE+b0c+1]=vb0.y;
        B[b0row*BSTRIDE+b0c+2]=vb0.z; B[b0row*BSTRIDE+b0c+3]=vb0.w;
        B[b1row*BSTRIDE+b1c+0]=vb1.x; B[b1row*BSTRIDE+b1c+1]=vb1.y;
        B[b1row*BSTRIDE+b1c+2]=vb1.z; B[b1row*BSTRIDE+b1c+3]=vb1.w;
    }
    __syncthreads();

    const int NITER = D_MODEL / 16;
    for (int it = 0; it < NITER; it++) {
        int buf = it & 1;
        uint4 va0, va1, vb0, vb1;
        bool more = (it + 1 < NITER);
        if (more) {
            int kt = (it + 1) * 16;
            va0 = *(const uint4*)(xr0 + kt);
            va1 = *(const uint4*)(xr1 + kt);
            vb0 = *(const uint4*)(w1e + (size_t)(kt + b0row) * D_FF + b0c);
            vb1 = *(const uint4*)(w1e + (size_t)(kt + b1row) * D_FF + b1c);
        }

        const unsigned* A = As[buf]; const unsigned* B = Bs[buf];
#pragma unroll
        for (int ks = 0; ks < 16; ks += 8) {
            unsigned af[4][4], bf[4][2];
#pragma unroll
            for (int i = 0; i < 4; i++) {
                int m = warp_m * 64 + i * 16;
                af[i][0] = A[(m + gid)     * ASTRIDE + ks + tig];
                af[i][1] = A[(m + gid + 8) * ASTRIDE + ks + tig];
                af[i][2] = A[(m + gid)     * ASTRIDE + ks + tig + 4];
                af[i][3] = A[(m + gid + 8) * ASTRIDE + ks + tig + 4];
            }
#pragma unroll
            for (int j = 0; j < 4; j++) {
                int n = warp_n * 32 + j * 8;
                bf[j][0] = B[(ks + tig)     * BSTRIDE + n + gid];
                bf[j][1] = B[(ks + tig + 4) * BSTRIDE + n + gid];
            }
#pragma unroll
            for (int i = 0; i < 4; i++)
#pragma unroll
                for (int j = 0; j < 4; j++)
                    mma_tf32(acc[i][j], af[i][0], af[i][1], af[i][2], af[i][3],
                             bf[j][0], bf[j][1]);
        }

        if (more) {
            unsigned* An = As[buf ^ 1]; unsigned* Bn = Bs[buf ^ 1];
            An[a0row*ASTRIDE+a0c+0]=va0.x; An[a0row*ASTRIDE+a0c+1]=va0.y;
            An[a0row*ASTRIDE+a0c+2]=va0.z; An[a0row*ASTRIDE+a0c+3]=va0.w;
            An[a1row*ASTRIDE+a1c+0]=va1.x; An[a1row*ASTRIDE+a1c+1]=va1.y;
            An[a1row*ASTRIDE+a1c+2]=va1.z; An[a1row*ASTRIDE+a1c+3]=va1.w;
            Bn[b0row*BSTRIDE+b0c+0]=vb0.x; Bn[b0row*BSTRIDE+b0c+1]=vb0.y;
            Bn[b0row*BSTRIDE+b0c+2]=vb0.z; Bn[b0row*BSTRIDE+b0c+3]=vb0.w;
            Bn[b1row*BSTRIDE+b1c+0]=vb1.x; Bn[b1row*BSTRIDE+b1c+1]=vb1.y;
            Bn[b1row*BSTRIDE+b1c+2]=vb1.z; Bn[b1row*BSTRIDE+b1c+3]=vb1.w;
        }
        __syncthreads();
    }

    // epilogue: + b1, exact gelu, tf32 store
#pragma unroll
    for (int i = 0; i < 4; i++) {
        int mrow = warp_m * 64 + i * 16 + gid;
#pragma unroll
        for (int half = 0; half < 2; half++) {
            int gr = row0 + mrow + half * 8;
            if (gr >= count) continue;
            unsigned* hrow = &g_h[((size_t)e * CAP + gr) * D_FF + col0];
#pragma unroll
            for (int j = 0; j < 4; j++) {
                int c = warp_n * 32 + j * 8 + tig * 2;
                float v0 = acc[i][j][half * 2 + 0] + b1[e * D_FF + col0 + c];
                float v1 = acc[i][j][half * 2 + 1] + b1[e * D_FF + col0 + c + 1];
                float g0 = 0.5f * v0 * (1.0f + erff(v0 * 0.70710678118654752f));
                float g1 = 0.5f * v1 * (1.0f + erff(v1 * 0.70710678118654752f));
                uint2 o; o.x = f2tf(g0); o.y = f2tf(g1);
                *(uint2*)(hrow + c) = o;
            }
        }
    }
}

// ---------------- FFN2: out += w * (h @ w2[e] + b2[e]) ----------------
__global__ __launch_bounds__(256, 2)
void ffn2_kernel(const float* __restrict__ b2, float* __restrict__ out) {
    __shared__ unsigned As[2][128 * ASTRIDE];
    __shared__ unsigned Bs[2][16 * BSTRIDE];
    __shared__ int   s_tok[128];
    __shared__ float s_w[128];

    int e = blockIdx.z;
    int count = g_counts[e];
    int row0 = blockIdx.y * 128;
    if (row0 >= count) return;
    int col0 = blockIdx.x * 128;

    int t = threadIdx.x;
    if (t < 128) {
        int gr = row0 + t;
        int idx = gr < count ? gr : count - 1;
        s_tok[t] = g_tokidx[e * CAP + idx];
        s_w[t]   = (gr < count) ? g_tokw[e * CAP + idx] : 0.0f;
    }
    __syncthreads();

    int lane = t & 31, wid = t >> 5;
    int warp_m = wid >> 2, warp_n = wid & 3;
    int gid = lane >> 2, tig = lane & 3;

    int a0row = t >> 2,            a0c = (t & 3) * 4;
    int a1row = (t + 256) >> 2,    a1c = a0c;
    int b0row = t >> 5,            b0c = (t & 31) * 4;
    int b1row = (t + 256) >> 5,    b1c = b0c;

    const unsigned* he  = g_h + ((size_t)e * CAP + row0) * D_FF;
    const unsigned* ar0 = he + (size_t)a0row * D_FF + a0c;
    const unsigned* ar1 = he + (size_t)a1row * D_FF + a1c;
    const unsigned* w2e = g_w2c + (size_t)e * D_FF * D_MODEL + col0;

    float acc[4][4][4];
#pragma unroll
    for (int i = 0; i < 4; i++)
#pragma unroll
        for (int j = 0; j < 4; j++)
#pragma unroll
            for (int q = 0; q < 4; q++) acc[i][j][q] = 0.0f;

    {
        uint4 va0 = *(const uint4*)(ar0);
        uint4 va1 = *(const uint4*)(ar1);
        uint4 vb0 = *(const uint4*)(w2e + (size_t)b0row * D_MODEL + b0c);
        uint4 vb1 = *(const uint4*)(w2e + (size_t)b1row * D_MODEL + b1c);
        unsigned* A = As[0]; unsigned* B = Bs[0];
        A[a0row*ASTRIDE+a0c+0]=va0.x; A[a0row*ASTRIDE+a0c+1]=va0.y;
        A[a0row*ASTRIDE+a0c+2]=va0.z; A[a0row*ASTRIDE+a0c+3]=va0.w;
        A[a1row*ASTRIDE+a1c+0]=va1.x; A[a1row*ASTRIDE+a1c+1]=va1.y;
        A[a1row*ASTRIDE+a1c+2]=va1.z; A[a1row*ASTRIDE+a1c+3]=va1.w;
        B[b0row*BSTRIDE+b0c+0]=vb0.x; B[b0row*BSTRIDE+b0c+1]=vb0.y;
        B[b0row*BSTRIDE+b0c+2]=vb0.z; B[b0row*BSTRIDE+b0c+3]=vb0.w;
        B[b1row*BSTRIDE+b1c+0]=vb1.x; B[b1row*BSTRIDE+b1c+1]=vb1.y;
        B[b1row*BSTRIDE+b1c+2]=vb1.z; B[b1row*BSTRIDE+b1c+3]=vb1.w;
    }
    __syncthreads();

    const int NITER = D_FF / 16;
    for (int it = 0; it < NITER; it++) {
        int buf = it & 1;
        uint4 va0, va1, vb0, vb1;
        bool more = (it + 1 < NITER);
        if (more) {
            int kt = (it + 1) * 16;
            va0 = *(const uint4*)(ar0 + kt);
            va1 = *(const uint4*)(ar1 + kt);
            vb0 = *(const uint4*)(w2e + (size_t)(kt + b0row) * D_MODEL + b0c);
            vb1 = *(const uint4*)(w2e + (size_t)(kt + b1row) * D_MODEL + b1c);
        }

        const unsigned* A = As[buf]; const unsigned* B = Bs[buf];
#pragma unroll
        for (int ks = 0; ks < 16; ks += 8) {
            unsigned af[4][4], bf[4][2];
#pragma unroll
            for (int i = 0; i < 4; i++) {
                int m = warp_m * 64 + i * 16;
                af[i][0] = A[(m + gid)     * ASTRIDE + ks + tig];
                af[i][1] = A[(m + gid + 8) * ASTRIDE + ks + tig];
                af[i][2] = A[(m + gid)     * ASTRIDE + ks + tig + 4];
                af[i][3] = A[(m + gid + 8) * ASTRIDE + ks + tig + 4];
            }
#pragma unroll
            for (int j = 0; j < 4; j++) {
                int n = warp_n * 32 + j * 8;
                bf[j][0] = B[(ks + tig)     * BSTRIDE + n + gid];
                bf[j][1] = B[(ks + tig + 4) * BSTRIDE + n + gid];
            }
#pragma unroll
            for (int i = 0; i < 4; i++)
#pragma unroll
                for (int j = 0; j < 4; j++)
                    mma_tf32(acc[i][j], af[i][0], af[i][1], af[i][2], af[i][3],
                             bf[j][0], bf[j][1]);
        }

        if (more) {
            unsigned* An = As[buf ^ 1]; unsigned* Bn = Bs[buf ^ 1];
            An[a0row*ASTRIDE+a0c+0]=va0.x; An[a0row*ASTRIDE+a0c+1]=va0.y;
            An[a0row*ASTRIDE+a0c+2]=va0.z; An[a0row*ASTRIDE+a0c+3]=va0.w;
            An[a1row*ASTRIDE+a1c+0]=va1.x; An[a1row*ASTRIDE+a1c+1]=va1.y;
            An[a1row*ASTRIDE+a1c+2]=va1.z; An[a1row*ASTRIDE+a1c+3]=va1.w;
            Bn[b0row*BSTRIDE+b0c+0]=vb0.x; Bn[b0row*BSTRIDE+b0c+1]=vb0.y;
            Bn[b0row*BSTRIDE+b0c+2]=vb0.z; Bn[b0row*BSTRIDE+b0c+3]=vb0.w;
            Bn[b1row*BSTRIDE+b1c+0]=vb1.x; Bn[b1row*BSTRIDE+b1c+1]=vb1.y;
            Bn[b1row*BSTRIDE+b1c+2]=vb1.z; Bn[b1row*BSTRIDE+b1c+3]=vb1.w;
        }
        __syncthreads();
    }

    // epilogue: weighted atomic scatter
#pragma unroll
    for (int i = 0; i < 4; i++) {
        int mrow = warp_m * 64 + i * 16 + gid;
#pragma unroll
        for (int half = 0; half < 2; half++) {
            int r = mrow + half * 8;
            int gr = row0 + r;
            if (gr >= count) continue;
            int tok = s_tok[r];
            float w  = s_w[r];
            float* orow = out + (size_t)tok * D_MODEL + col0;
#pragma unroll
            for (int j = 0; j < 4; j++) {
                int c = warp_n * 32 + j * 8 + tig * 2;
                float v0 = acc[i][j][half * 2 + 0] + b2[e * D_MODEL + col0 + c];
                float v1 = acc[i][j][half * 2 + 1] + b2[e * D_MODEL + col0 + c + 1];
                atomicAdd(&orow[c],     w * v0);
                atomicAdd(&orow[c + 1], w * v1);
            }
        }
    }
}

// ---------------- aux loss ----------------
__global__ void aux_kernel(float* out_aux, float invT) {
    if (threadIdx.x == 0 && blockIdx.x == 0) {
        float m[NE]; float mu = 0.0f;
#pragma unroll
        for (int e = 0; e < NE; e++) { m[e] = g_sumprobs[e] * invT; mu += m[e]; }
        mu *= (1.0f / NE);
        float v = 0.0f;
#pragma unroll
        for (int e = 0; e < NE; e++) { float d = m[e] - mu; v += d * d; }
        *out_aux = v / (NE - 1);
    }
}

// ---------------- launch ----------------
extern "C" void kernel_launch(void* const* d_in, const int* in_sizes, int n_in,
                              void* d_out, int out_size) {
    const float* x  = (const float*)d_in[0];
    const float* rw = (const float*)d_in[1];
    const float* rb = (const float*)d_in[2];
    const float* w1 = (const float*)d_in[3];
    const float* b1 = (const float*)d_in[4];
    const float* w2 = (const float*)d_in[5];
    const float* b2 = (const float*)d_in[6];
    float* out = (float*)d_out;

    int T = in_sizes[0] / D_MODEL;

    cudaMemsetAsync(d_out, 0, (size_t)T * D_MODEL * sizeof(float));
    zero_small_kernel<<<1, 32>>>();
    router_kernel<<<(T + 3) / 4, 128>>>(x, rw, rb, T);

    // tf32 pre-conversion (destinations referenced in device code)
    convx_kernel<<<2048, 256>>>(x, (size_t)T * D_MODEL / 4);
    convw1_kernel<<<8192, 256>>>(w1, (size_t)NE * D_MODEL * D_FF / 4);
    convw2_kernel<<<8192, 256>>>(w2, (size_t)NE * D_FF * D_MODEL / 4);

    dim3 g1(D_FF / 128, CAP / 128, NE);
    ffn1_kernel<<<g1, 256>>>(b1);

    dim3 g2(D_MODEL / 128, CAP / 128, NE);
    ffn2_kernel<<<g2, 256>>>(b2, out);

    if (out_size > T * D_MODEL) {
        aux_kernel<<<1, 32>>>(out + (size_t)T * D_MODEL, 1.0f / (float)T);
    }
}

// round 8
// speedup vs baseline: 3.5808x; 1.2442x over previous
#include <cuda_runtime.h>
#include <math.h>
#include <stdint.h>

#define D_MODEL 1024
#define D_FF    4096
#define NE      8
#define CAP     4096
#define BK      32          // halves per K-tile

// ---------------- device scratch (all fp16 payloads stored as u32 words) ----------------
__device__ int      g_counts[NE];
__device__ float    g_sumprobs[NE];
__device__ int      g_tokidx[NE * CAP];
__device__ float    g_tokw[NE * CAP];
__device__ unsigned g_xh[(size_t)CAP * D_MODEL / 2];          // fp16 tokens
__device__ unsigned g_w1h[(size_t)NE * D_MODEL * D_FF / 2];   // fp16 w1 [e][k][n]
__device__ unsigned g_w2h[(size_t)NE * D_FF * D_MODEL / 2];   // fp16 w2 [e][k][n]
__device__ unsigned g_hh[(size_t)NE * CAP * D_FF / 2];        // fp16 hidden

__global__ void zero_small_kernel() {
    int t = threadIdx.x;
    if (t < NE) { g_counts[t] = 0; g_sumprobs[t] = 0.0f; }
}

// ---------------- helpers ----------------
__device__ __forceinline__ unsigned pack_h2(float lo, float hi) {
    unsigned u;
    asm("cvt.rn.f16x2.f32 %0, %1, %2;" : "=r"(u) : "f"(hi), "f"(lo));
    return u;
}

__device__ __forceinline__ uint32_t smem_u32(const void* p) {
    uint32_t a;
    asm("{ .reg .u64 t; cvta.to.shared.u64 t, %1; cvt.u32.u64 %0, t; }" : "=r"(a) : "l"(p));
    return a;
}

__device__ __forceinline__ void mma_f16(float c[4],
                                        unsigned a0, unsigned a1, unsigned a2, unsigned a3,
                                        unsigned b0, unsigned b1) {
    asm volatile(
        "mma.sync.aligned.m16n8k16.row.col.f32.f16.f16.f32 "
        "{%0,%1,%2,%3}, {%4,%5,%6,%7}, {%8,%9}, {%0,%1,%2,%3};\n"
        : "+f"(c[0]), "+f"(c[1]), "+f"(c[2]), "+f"(c[3])
        : "r"(a0), "r"(a1), "r"(a2), "r"(a3), "r"(b0), "r"(b1));
}

#define LDMX4(r0, r1, r2, r3, addr) \
    asm volatile("ldmatrix.sync.aligned.m8n8.x4.shared.b16 {%0,%1,%2,%3}, [%4];" \
        : "=r"(r0), "=r"(r1), "=r"(r2), "=r"(r3) : "r"(addr))

#define LDMX4T(r0, r1, r2, r3, addr) \
    asm volatile("ldmatrix.sync.aligned.m8n8.x4.trans.shared.b16 {%0,%1,%2,%3}, [%4];" \
        : "=r"(r0), "=r"(r1), "=r"(r2), "=r"(r3) : "r"(addr))

// smem geometry (halves): A rows stride 40 (80B), B rows stride 136 (272B)
#define ASTRH 40
#define BSTRH 136
#define AWRD  (128 * ASTRH / 2)   // 2560 words per A buffer
#define BWRD  (BK * BSTRH / 2)    // 2176 words per B buffer
#define OFF_A(b) (256 + (b) * AWRD)
#define OFF_B(b) (256 + 2 * AWRD + (b) * BWRD)
#define SMEM_WORDS (256 + 2 * AWRD + 2 * BWRD)   // 9728 words = 38912 B

// ---------------- fp16 pre-conversion (dst referenced in device code!) ----------------
__device__ __forceinline__ void conv_body(const float* __restrict__ in,
                                          unsigned* __restrict__ out, size_t n4) {
    size_t i = (size_t)blockIdx.x * blockDim.x + threadIdx.x;
    size_t stride = (size_t)gridDim.x * blockDim.x;
    for (; i < n4; i += stride) {
        float4 v = ((const float4*)in)[i];
        uint2 o;
        o.x = pack_h2(v.x, v.y);
        o.y = pack_h2(v.z, v.w);
        ((uint2*)out)[i] = o;
    }
}
__global__ void convx_kernel(const float* __restrict__ in, size_t n4)  { conv_body(in, g_xh, n4); }
__global__ void convw1_kernel(const float* __restrict__ in, size_t n4) { conv_body(in, g_w1h, n4); }
__global__ void convw2_kernel(const float* __restrict__ in, size_t n4) { conv_body(in, g_w2h, n4); }

// ---------------- router ----------------
__global__ void router_kernel(const float* __restrict__ x,
                              const float* __restrict__ rw,
                              const float* __restrict__ rb,
                              int T) {
    __shared__ float s_rw[NE * D_MODEL];
    for (int i = threadIdx.x; i < D_MODEL * NE; i += blockDim.x) {
        int k = i / NE, e = i % NE;
        s_rw[e * D_MODEL + k] = rw[i];
    }
    __syncthreads();

    int warp = threadIdx.x >> 5;
    int lane = threadIdx.x & 31;
    int tok = blockIdx.x * (blockDim.x >> 5) + warp;
    if (tok >= T) return;

    const float* xr = x + (size_t)tok * D_MODEL;
    float acc[NE];
#pragma unroll
    for (int e = 0; e < NE; e++) acc[e] = 0.0f;
    for (int k = lane; k < D_MODEL; k += 32) {
        float xv = xr[k];
#pragma unroll
        for (int e = 0; e < NE; e++) acc[e] += xv * s_rw[e * D_MODEL + k];
    }
#pragma unroll
    for (int e = 0; e < NE; e++) {
#pragma unroll
        for (int off = 16; off > 0; off >>= 1)
            acc[e] += __shfl_xor_sync(0xFFFFFFFFu, acc[e], off);
    }

    if (lane == 0) {
        float logit[NE]; float m = -1e30f;
#pragma unroll
        for (int e = 0; e < NE; e++) { logit[e] = acc[e] + rb[e]; m = fmaxf(m, logit[e]); }
        float p[NE]; float s = 0.0f;
#pragma unroll
        for (int e = 0; e < NE; e++) { p[e] = __expf(logit[e] - m); s += p[e]; }
        float inv = 1.0f / s;
#pragma unroll
        for (int e = 0; e < NE; e++) p[e] *= inv;
#pragma unroll
        for (int e = 0; e < NE; e++) atomicAdd(&g_sumprobs[e], p[e]);

        int i1 = 0; float v1 = p[0];
#pragma unroll
        for (int e = 1; e < NE; e++) if (p[e] > v1) { v1 = p[e]; i1 = e; }
        int i2 = -1; float v2 = -1.0f;
#pragma unroll
        for (int e = 0; e < NE; e++) if (e != i1 && p[e] > v2) { v2 = p[e]; i2 = e; }

        float wn = 1.0f / (v1 + v2);
        int s1 = atomicAdd(&g_counts[i1], 1);
        g_tokidx[i1 * CAP + s1] = tok;  g_tokw[i1 * CAP + s1] = v1 * wn;
        int s2 = atomicAdd(&g_counts[i2], 1);
        g_tokidx[i2 * CAP + s2] = tok;  g_tokw[i2 * CAP + s2] = v2 * wn;
    }
}

// ---------------- FFN1: h = fp16(gelu(X_e @ w1[e] + b1[e])) ----------------
__global__ __launch_bounds__(256, 2)
void ffn1_kernel(const float* __restrict__ b1) {
    __shared__ unsigned smem[SMEM_WORDS];
    int* s_tok = (int*)smem;

    int e = blockIdx.z;
    int count = g_counts[e];
    int row0 = blockIdx.y * 128;
    if (row0 >= count) return;
    int col0 = blockIdx.x * 128;

    int t = threadIdx.x;
    if (t < 128) {
        int gr = row0 + t;
        s_tok[t] = g_tokidx[e * CAP + (gr < count ? gr : count - 1)];
    }
    __syncthreads();

    int lane = t & 31, wid = t >> 5;
    int warp_m = wid >> 2, warp_n = wid & 3;
    int gid = lane >> 2, tig = lane & 3;
    int lrow = (lane & 7) + (lane & 8);      // 0..15
    int lk   = ((lane >> 4) & 1) * 8;        // 0 or 8

    uint32_t sb = smem_u32(smem);

    // staging geometry: A 512 chunks (i<2): row=cid&127, chunk=cid>>7
    //                   B 512 chunks (i<2): krow=cid&31, chunk=cid>>5
    const unsigned* aS[2]; uint32_t aDw[2];
    const unsigned* bS[2]; uint32_t bDw[2];
    const unsigned* w1e = g_w1h + (size_t)e * (D_MODEL * D_FF / 2) + col0 / 2;
#pragma unroll
    for (int i = 0; i < 2; i++) {
        int cid = t + 256 * i;
        int arow = cid & 127, ach = cid >> 7;
        aS[i]  = g_xh + (size_t)s_tok[arow] * (D_MODEL / 2) + ach * 4;
        aDw[i] = arow * (ASTRH / 2) + ach * 4;
        int brow = cid & 31, bch = cid >> 5;
        bS[i]  = w1e + (size_t)brow * (D_FF / 2) + bch * 4;
        bDw[i] = brow * (BSTRH / 2) + bch * 4;
    }

    float acc[4][4][4];
#pragma unroll
    for (int i = 0; i < 4; i++)
#pragma unroll
        for (int j = 0; j < 4; j++)
#pragma unroll
            for (int q = 0; q < 4; q++) acc[i][j][q] = 0.0f;

    // prologue: tile 0 -> buffer 0
#pragma unroll
    for (int i = 0; i < 2; i++) {
        *(uint4*)(smem + OFF_A(0) + aDw[i]) = *(const uint4*)(aS[i]);
        *(uint4*)(smem + OFF_B(0) + bDw[i]) = *(const uint4*)(bS[i]);
    }
    __syncthreads();

    const int NIT = D_MODEL / BK;
    int buf = 0;
    for (int it = 0; it < NIT; it++) {
        uint4 va[2], vb[2];
        bool more = (it + 1 < NIT);
        if (more) {
            int ktw = (it + 1) * (BK / 2);                 // words
#pragma unroll
            for (int i = 0; i < 2; i++) {
                va[i] = *(const uint4*)(aS[i] + ktw);
                vb[i] = *(const uint4*)(bS[i] + (size_t)(it + 1) * BK * (D_FF / 2));
            }
        }

        uint32_t sbA = sb + OFF_A(buf) * 4;
        uint32_t sbB = sb + OFF_B(buf) * 4;
#pragma unroll
        for (int ks = 0; ks < BK; ks += 16) {
            unsigned af[4][4], bf[4][2];
#pragma unroll
            for (int i = 0; i < 4; i++) {
                int m = warp_m * 64 + i * 16;
                uint32_t ad = sbA + (m + lrow) * (ASTRH * 2) + (ks + lk) * 2;
                LDMX4(af[i][0], af[i][1], af[i][2], af[i][3], ad);
            }
#pragma unroll
            for (int jj = 0; jj < 2; jj++) {
                uint32_t bd = sbB + (ks + lrow) * (BSTRH * 2)
                            + (warp_n * 32 + jj * 16 + lk) * 2;
                LDMX4T(bf[jj*2][0], bf[jj*2][1], bf[jj*2+1][0], bf[jj*2+1][1], bd);
            }
#pragma unroll
            for (int i = 0; i < 4; i++)
#pragma unroll
                for (int j = 0; j < 4; j++)
                    mma_f16(acc[i][j], af[i][0], af[i][1], af[i][2], af[i][3],
                            bf[j][0], bf[j][1]);
        }

        if (more) {
#pragma unroll
            for (int i = 0; i < 2; i++) {
                *(uint4*)(smem + OFF_A(buf ^ 1) + aDw[i]) = va[i];
                *(uint4*)(smem + OFF_B(buf ^ 1) + bDw[i]) = vb[i];
            }
        }
        __syncthreads();
        buf ^= 1;
    }

    // epilogue: + b1, exact gelu, fp16 store
#pragma unroll
    for (int i = 0; i < 4; i++) {
        int mrow = warp_m * 64 + i * 16 + gid;
#pragma unroll
        for (int half = 0; half < 2; half++) {
            int gr = row0 + mrow + half * 8;
            if (gr >= count) continue;
            unsigned* hrow = g_hh + ((size_t)e * CAP + gr) * (D_FF / 2) + col0 / 2;
#pragma unroll
            for (int j = 0; j < 4; j++) {
                int c = warp_n * 32 + j * 8 + tig * 2;
                float v0 = acc[i][j][half * 2 + 0] + b1[e * D_FF + col0 + c];
                float v1 = acc[i][j][half * 2 + 1] + b1[e * D_FF + col0 + c + 1];
                float g0 = 0.5f * v0 * (1.0f + erff(v0 * 0.70710678118654752f));
                float g1 = 0.5f * v1 * (1.0f + erff(v1 * 0.70710678118654752f));
                hrow[c / 2] = pack_h2(g0, g1);
            }
        }
    }
}

// ---------------- FFN2: out += w * (h @ w2[e] + b2[e]) ----------------
__global__ __launch_bounds__(256, 2)
void ffn2_kernel(const float* __restrict__ b2, float* __restrict__ out) {
    __shared__ unsigned smem[SMEM_WORDS];
    int*   s_tok = (int*)smem;
    float* s_w   = (float*)(smem + 128);

    int e = blockIdx.z;
    int count = g_counts[e];
    int row0 = blockIdx.y * 128;
    if (row0 >= count) return;
    int col0 = blockIdx.x * 128;

    int t = threadIdx.x;
    if (t < 128) {
        int gr = row0 + t;
        int idx = gr < count ? gr : count - 1;
        s_tok[t] = g_tokidx[e * CAP + idx];
        s_w[t]   = (gr < count) ? g_tokw[e * CAP + idx] : 0.0f;
    }
    __syncthreads();

    int lane = t & 31, wid = t >> 5;
    int warp_m = wid >> 2, warp_n = wid & 3;
    int gid = lane >> 2, tig = lane & 3;
    int lrow = (lane & 7) + (lane & 8);
    int lk   = ((lane >> 4) & 1) * 8;

    uint32_t sb = smem_u32(smem);

    const unsigned* he  = g_hh + ((size_t)e * CAP + row0) * (D_FF / 2);
    const unsigned* w2e = g_w2h + (size_t)e * (D_FF * D_MODEL / 2) + col0 / 2;

    const unsigned* aS[2]; uint32_t aDw[2];
    const unsigned* bS[2]; uint32_t bDw[2];
#pragma unroll
    for (int i = 0; i < 2; i++) {
        int cid = t + 256 * i;
        int arow = cid & 127, ach = cid >> 7;
        aS[i]  = he + (size_t)arow * (D_FF / 2) + ach * 4;
        aDw[i] = arow * (ASTRH / 2) + ach * 4;
        int brow = cid & 31, bch = cid >> 5;
        bS[i]  = w2e + (size_t)brow * (D_MODEL / 2) + bch * 4;
        bDw[i] = brow * (BSTRH / 2) + bch * 4;
    }

    float acc[4][4][4];
#pragma unroll
    for (int i = 0; i < 4; i++)
#pragma unroll
        for (int j = 0; j < 4; j++)
#pragma unroll
            for (int q = 0; q < 4; q++) acc[i][j][q] = 0.0f;

#pragma unroll
    for (int i = 0; i < 2; i++) {
        *(uint4*)(smem + OFF_A(0) + aDw[i]) = *(const uint4*)(aS[i]);
        *(uint4*)(smem + OFF_B(0) + bDw[i]) = *(const uint4*)(bS[i]);
    }
    __syncthreads();

    const int NIT = D_FF / BK;
    int buf = 0;
    for (int it = 0; it < NIT; it++) {
        uint4 va[2], vb[2];
        bool more = (it + 1 < NIT);
        if (more) {
            int ktw = (it + 1) * (BK / 2);
#pragma unroll
            for (int i = 0; i < 2; i++) {
                va[i] = *(const uint4*)(aS[i] + ktw);
                vb[i] = *(const uint4*)(bS[i] + (size_t)(it + 1) * BK * (D_MODEL / 2));
            }
        }

        uint32_t sbA = sb + OFF_A(buf) * 4;
        uint32_t sbB = sb + OFF_B(buf) * 4;
#pragma unroll
        for (int ks = 0; ks < BK; ks += 16) {
            unsigned af[4][4], bf[4][2];
#pragma unroll
            for (int i = 0; i < 4; i++) {
                int m = warp_m * 64 + i * 16;
                uint32_t ad = sbA + (m + lrow) * (ASTRH * 2) + (ks + lk) * 2;
                LDMX4(af[i][0], af[i][1], af[i][2], af[i][3], ad);
            }
#pragma unroll
            for (int jj = 0; jj < 2; jj++) {
                uint32_t bd = sbB + (ks + lrow) * (BSTRH * 2)
                            + (warp_n * 32 + jj * 16 + lk) * 2;
                LDMX4T(bf[jj*2][0], bf[jj*2][1], bf[jj*2+1][0], bf[jj*2+1][1], bd);
            }
#pragma unroll
            for (int i = 0; i < 4; i++)
#pragma unroll
                for (int j = 0; j < 4; j++)
                    mma_f16(acc[i][j], af[i][0], af[i][1], af[i][2], af[i][3],
                            bf[j][0], bf[j][1]);
        }

        if (more) {
#pragma unroll
            for (int i = 0; i < 2; i++) {
                *(uint4*)(smem + OFF_A(buf ^ 1) + aDw[i]) = va[i];
                *(uint4*)(smem + OFF_B(buf ^ 1) + bDw[i]) = vb[i];
            }
        }
        __syncthreads();
        buf ^= 1;
    }

    // epilogue: weighted atomic scatter
#pragma unroll
    for (int i = 0; i < 4; i++) {
        int mrow = warp_m * 64 + i * 16 + gid;
#pragma unroll
        for (int half = 0; half < 2; half++) {
            int r = mrow + half * 8;
            int gr = row0 + r;
            if (gr >= count) continue;
            int tok = s_tok[r];
            float w  = s_w[r];
            float* orow = out + (size_t)tok * D_MODEL + col0;
#pragma unroll
            for (int j = 0; j < 4; j++) {
                int c = warp_n * 32 + j * 8 + tig * 2;
                float v0 = acc[i][j][half * 2 + 0] + b2[e * D_MODEL + col0 + c];
                float v1 = acc[i][j][half * 2 + 1] + b2[e * D_MODEL + col0 + c + 1];
                atomicAdd(&orow[c],     w * v0);
                atomicAdd(&orow[c + 1], w * v1);
            }
        }
    }
}

// ---------------- aux loss ----------------
__global__ void aux_kernel(float* out_aux, float invT) {
    if (threadIdx.x == 0 && blockIdx.x == 0) {
        float m[NE]; float mu = 0.0f;
#pragma unroll
        for (int e = 0; e < NE; e++) { m[e] = g_sumprobs[e] * invT; mu += m[e]; }
        mu *= (1.0f / NE);
        float v = 0.0f;
#pragma unroll
        for (int e = 0; e < NE; e++) { float d = m[e] - mu; v += d * d; }
        *out_aux = v / (NE - 1);
    }
}

// ---------------- launch ----------------
extern "C" void kernel_launch(void* const* d_in, const int* in_sizes, int n_in,
                              void* d_out, int out_size) {
    const float* x  = (const float*)d_in[0];
    const float* rw = (const float*)d_in[1];
    const float* rb = (const float*)d_in[2];
    const float* w1 = (const float*)d_in[3];
    const float* b1 = (const float*)d_in[4];
    const float* w2 = (const float*)d_in[5];
    const float* b2 = (const float*)d_in[6];
    float* out = (float*)d_out;

    int T = in_sizes[0] / D_MODEL;

    cudaMemsetAsync(d_out, 0, (size_t)T * D_MODEL * sizeof(float));
    zero_small_kernel<<<1, 32>>>();
    router_kernel<<<(T + 3) / 4, 128>>>(x, rw, rb, T);

    convx_kernel<<<2048, 256>>>(x, (size_t)T * D_MODEL / 4);
    convw1_kernel<<<8192, 256>>>(w1, (size_t)NE * D_MODEL * D_FF / 4);
    convw2_kernel<<<8192, 256>>>(w2, (size_t)NE * D_FF * D_MODEL / 4);

    dim3 g1(D_FF / 128, CAP / 128, NE);
    ffn1_kernel<<<g1, 256>>>(b1);

    dim3 g2(D_MODEL / 128, CAP / 128, NE);
    ffn2_kernel<<<g2, 256>>>(b2, out);

    if (out_size > T * D_MODEL) {
        aux_kernel<<<1, 32>>>(out + (size_t)T * D_MODEL, 1.0f / (float)T);
    }
}

// round 9
// speedup vs baseline: 5.9648x; 1.6658x over previous
#include <cuda_runtime.h>
#include <math.h>
#include <stdint.h>

#define D_MODEL 1024
#define D_FF    4096
#define NE      8
#define CAP     4096
#define BK      64          // halves per K-tile

// ---------------- device scratch (fp16 payloads stored as u32 words) ----------------
__device__ int      g_counts[NE];
__device__ float    g_sumprobs[NE];
__device__ int      g_tokidx[NE * CAP];
__device__ float    g_tokw[NE * CAP];
__device__ unsigned g_xh[(size_t)CAP * D_MODEL / 2];          // fp16 tokens
__device__ unsigned g_w1h[(size_t)NE * D_MODEL * D_FF / 2];   // fp16 w1 [e][k][n]
__device__ unsigned g_w2h[(size_t)NE * D_FF * D_MODEL / 2];   // fp16 w2 [e][k][n]
__device__ unsigned g_hh[(size_t)NE * CAP * D_FF / 2];        // fp16 hidden

__global__ void zero_small_kernel() {
    int t = threadIdx.x;
    if (t < NE) { g_counts[t] = 0; g_sumprobs[t] = 0.0f; }
}

// ---------------- helpers ----------------
__device__ __forceinline__ unsigned pack_h2(float lo, float hi) {
    unsigned u;
    asm("cvt.rn.f16x2.f32 %0, %1, %2;" : "=r"(u) : "f"(hi), "f"(lo));
    return u;
}

__device__ __forceinline__ uint32_t smem_u32(const void* p) {
    uint32_t a;
    asm("{ .reg .u64 t; cvta.to.shared.u64 t, %1; cvt.u32.u64 %0, t; }" : "=r"(a) : "l"(p));
    return a;
}

__device__ __forceinline__ void mma_f16(float c[4],
                                        unsigned a0, unsigned a1, unsigned a2, unsigned a3,
                                        unsigned b0, unsigned b1) {
    asm volatile(
        "mma.sync.aligned.m16n8k16.row.col.f32.f16.f16.f32 "
        "{%0,%1,%2,%3}, {%4,%5,%6,%7}, {%8,%9}, {%0,%1,%2,%3};\n"
        : "+f"(c[0]), "+f"(c[1]), "+f"(c[2]), "+f"(c[3])
        : "r"(a0), "r"(a1), "r"(a2), "r"(a3), "r"(b0), "r"(b1));
}

#define LDMX4(r0, r1, r2, r3, addr) \
    asm volatile("ldmatrix.sync.aligned.m8n8.x4.shared.b16 {%0,%1,%2,%3}, [%4];" \
        : "=r"(r0), "=r"(r1), "=r"(r2), "=r"(r3) : "r"(addr))

#define LDMX4T(r0, r1, r2, r3, addr) \
    asm volatile("ldmatrix.sync.aligned.m8n8.x4.trans.shared.b16 {%0,%1,%2,%3}, [%4];" \
        : "=r"(r0), "=r"(r1), "=r"(r2), "=r"(r3) : "r"(addr))

__device__ __forceinline__ void cp16(uint32_t dst, const void* src) {
    asm volatile("cp.async.cg.shared.global [%0], [%1], 16;" :: "r"(dst), "l"(src));
}
#define CP_COMMIT() asm volatile("cp.async.commit_group;" ::: "memory")
#define CP_WAIT0()  asm volatile("cp.async.wait_group 0;" ::: "memory")

// smem geometry (bytes): ctrl 1KB | A0 | A1 | B0 | B1
// A row pitch 144B (72 halves: 64 + 8 pad; 144 % 128 = 16 -> ldmatrix conflict-free)
// B row pitch 272B (136 halves: 128 + 8 pad; 272 % 128 = 16 -> conflict-free)
#define APITCH 144
#define BPITCH 272
#define ABYTES (128 * APITCH)     // 18432
#define BBYTES (BK * BPITCH)      // 17408
#define OFFA(b) (1024 + (b) * ABYTES)
#define OFFB(b) (1024 + 2 * ABYTES + (b) * BBYTES)
#define DYN_BYTES (1024 + 2 * ABYTES + 2 * BBYTES)   // 72704

// ---------------- fp16 pre-conversion (dst referenced in device code!) ----------------
__device__ __forceinline__ void conv_body(const float* __restrict__ in,
                                          unsigned* __restrict__ out, size_t n4) {
    size_t i = (size_t)blockIdx.x * blockDim.x + threadIdx.x;
    size_t stride = (size_t)gridDim.x * blockDim.x;
    for (; i < n4; i += stride) {
        float4 v = ((const float4*)in)[i];
        uint2 o;
        o.x = pack_h2(v.x, v.y);
        o.y = pack_h2(v.z, v.w);
        ((uint2*)out)[i] = o;
    }
}
__global__ void convx_kernel(const float* __restrict__ in, size_t n4)  { conv_body(in, g_xh, n4); }
__global__ void convw1_kernel(const float* __restrict__ in, size_t n4) { conv_body(in, g_w1h, n4); }
__global__ void convw2_kernel(const float* __restrict__ in, size_t n4) { conv_body(in, g_w2h, n4); }

// ---------------- router ----------------
__global__ void router_kernel(const float* __restrict__ x,
                              const float* __restrict__ rw,
                              const float* __restrict__ rb,
                              int T) {
    __shared__ float s_rw[NE * D_MODEL];
    for (int i = threadIdx.x; i < D_MODEL * NE; i += blockDim.x) {
        int k = i / NE, e = i % NE;
        s_rw[e * D_MODEL + k] = rw[i];
    }
    __syncthreads();

    int warp = threadIdx.x >> 5;
    int lane = threadIdx.x & 31;
    int tok = blockIdx.x * (blockDim.x >> 5) + warp;
    if (tok >= T) return;

    const float* xr = x + (size_t)tok * D_MODEL;
    float acc[NE];
#pragma unroll
    for (int e = 0; e < NE; e++) acc[e] = 0.0f;
    for (int k = lane; k < D_MODEL; k += 32) {
        float xv = xr[k];
#pragma unroll
        for (int e = 0; e < NE; e++) acc[e] += xv * s_rw[e * D_MODEL + k];
    }
#pragma unroll
    for (int e = 0; e < NE; e++) {
#pragma unroll
        for (int off = 16; off > 0; off >>= 1)
            acc[e] += __shfl_xor_sync(0xFFFFFFFFu, acc[e], off);
    }

    if (lane == 0) {
        float logit[NE]; float m = -1e30f;
#pragma unroll
        for (int e = 0; e < NE; e++) { logit[e] = acc[e] + rb[e]; m = fmaxf(m, logit[e]); }
        float p[NE]; float s = 0.0f;
#pragma unroll
        for (int e = 0; e < NE; e++) { p[e] = __expf(logit[e] - m); s += p[e]; }
        float inv = 1.0f / s;
#pragma unroll
        for (int e = 0; e < NE; e++) p[e] *= inv;
#pragma unroll
        for (int e = 0; e < NE; e++) atomicAdd(&g_sumprobs[e], p[e]);

        int i1 = 0; float v1 = p[0];
#pragma unroll
        for (int e = 1; e < NE; e++) if (p[e] > v1) { v1 = p[e]; i1 = e; }
        int i2 = -1; float v2 = -1.0f;
#pragma unroll
        for (int e = 0; e < NE; e++) if (e != i1 && p[e] > v2) { v2 = p[e]; i2 = e; }

        float wn = 1.0f / (v1 + v2);
        int s1 = atomicAdd(&g_counts[i1], 1);
        g_tokidx[i1 * CAP + s1] = tok;  g_tokw[i1 * CAP + s1] = v1 * wn;
        int s2 = atomicAdd(&g_counts[i2], 1);
        g_tokidx[i2 * CAP + s2] = tok;  g_tokw[i2 * CAP + s2] = v2 * wn;
    }
}

// ---------------- FFN1: h = fp16(gelu(X_e @ w1[e] + b1[e])) ----------------
__global__ __launch_bounds__(256, 2)
void ffn1_kernel(const float* __restrict__ b1) {
    extern __shared__ unsigned smem[];
    int* s_tok = (int*)smem;

    int e = blockIdx.z;
    int count = g_counts[e];
    int row0 = blockIdx.y * 128;
    if (row0 >= count) return;
    int col0 = blockIdx.x * 128;

    int t = threadIdx.x;
    if (t < 128) {
        int gr = row0 + t;
        s_tok[t] = g_tokidx[e * CAP + (gr < count ? gr : count - 1)];
    }
    __syncthreads();

    int lane = t & 31, wid = t >> 5;
    int warp_m = wid >> 2, warp_n = wid & 3;
    int gid = lane >> 2, tig = lane & 3;
    int lrow = (lane & 7) + (lane & 8);      // 0..15
    int lk   = ((lane >> 4) & 1) * 8;        // 0 or 8

    uint32_t sb = smem_u32(smem);

    // staging geometry (cp.async, 16B chunks), anchored at buffer 0:
    // A: 128 rows x 8 chunks -> cid = t+256*i: arow=cid>>3, ach=cid&7
    // B: 64 rows x 16 chunks -> brow=cid>>4, bch=cid&15
    const unsigned* aS[4]; uint32_t aD[4];
    const unsigned* bS[4]; uint32_t bD[4];
    const unsigned* w1e = g_w1h + (size_t)e * (D_MODEL * D_FF / 2) + col0 / 2;
#pragma unroll
    for (int i = 0; i < 4; i++) {
        int cid = t + 256 * i;
        int arow = cid >> 3, ach = cid & 7;
        aS[i] = g_xh + (size_t)s_tok[arow] * (D_MODEL / 2) + ach * 4;
        aD[i] = sb + OFFA(0) + arow * APITCH + ach * 16;
        int brow = cid >> 4, bch = cid & 15;
        bS[i] = w1e + (size_t)brow * (D_FF / 2) + bch * 4;
        bD[i] = sb + OFFB(0) + brow * BPITCH + bch * 16;
    }

    float acc[4][4][4];
#pragma unroll
    for (int i = 0; i < 4; i++)
#pragma unroll
        for (int j = 0; j < 4; j++)
#pragma unroll
            for (int q = 0; q < 4; q++) acc[i][j][q] = 0.0f;

    // prologue: tile 0 -> buffer 0
#pragma unroll
    for (int i = 0; i < 4; i++) { cp16(aD[i], aS[i]); cp16(bD[i], bS[i]); }
    CP_COMMIT();

    const int NIT = D_MODEL / BK;   // 16
    int buf = 0;
    for (int it = 0; it < NIT; it++) {
        CP_WAIT0();
        __syncthreads();
        if (it + 1 < NIT) {
            int ktw = (it + 1) * (BK / 2);                     // word offset in A rows
            uint32_t as = (buf ^ 1) * ABYTES;
            uint32_t bs = (buf ^ 1) * BBYTES;
#pragma unroll
            for (int i = 0; i < 4; i++) {
                cp16(aD[i] + as, aS[i] + ktw);
                cp16(bD[i] + bs, bS[i] + (size_t)(it + 1) * BK * (D_FF / 2));
            }
            CP_COMMIT();
        }

        uint32_t sbA = sb + OFFA(buf);
        uint32_t sbB = sb + OFFB(buf);
#pragma unroll
        for (int ks = 0; ks < BK; ks += 16) {
            unsigned af[4][4], bf[4][2];
#pragma unroll
            for (int i = 0; i < 4; i++) {
                int m = warp_m * 64 + i * 16;
                uint32_t ad = sbA + (m + lrow) * APITCH + (ks + lk) * 2;
                LDMX4(af[i][0], af[i][1], af[i][2], af[i][3], ad);
            }
#pragma unroll
            for (int jj = 0; jj < 2; jj++) {
                uint32_t bd = sbB + (ks + lrow) * BPITCH
                            + (warp_n * 32 + jj * 16 + lk) * 2;
                LDMX4T(bf[jj*2][0], bf[jj*2][1], bf[jj*2+1][0], bf[jj*2+1][1], bd);
            }
#pragma unroll
            for (int i = 0; i < 4; i++)
#pragma unroll
                for (int j = 0; j < 4; j++)
                    mma_f16(acc[i][j], af[i][0], af[i][1], af[i][2], af[i][3],
                            bf[j][0], bf[j][1]);
        }
        buf ^= 1;
    }

    // epilogue: + b1, exact gelu, fp16 store
#pragma unroll
    for (int i = 0; i < 4; i++) {
        int mrow = warp_m * 64 + i * 16 + gid;
#pragma unroll
        for (int half = 0; half < 2; half++) {
            int gr = row0 + mrow + half * 8;
            if (gr >= count) continue;
            unsigned* hrow = g_hh + ((size_t)e * CAP + gr) * (D_FF / 2) + col0 / 2;
#pragma unroll
            for (int j = 0; j < 4; j++) {
                int c = warp_n * 32 + j * 8 + tig * 2;
                float v0 = acc[i][j][half * 2 + 0] + b1[e * D_FF + col0 + c];
                float v1 = acc[i][j][half * 2 + 1] + b1[e * D_FF + col0 + c + 1];
                float g0 = 0.5f * v0 * (1.0f + erff(v0 * 0.70710678118654752f));
                float g1 = 0.5f * v1 * (1.0f + erff(v1 * 0.70710678118654752f));
                hrow[c / 2] = pack_h2(g0, g1);
            }
        }
    }
}

// ---------------- FFN2: out += w * (h @ w2[e] + b2[e]) ----------------
__global__ __launch_bounds__(256, 2)
void ffn2_kernel(const float* __restrict__ b2, float* __restrict__ out) {
    extern __shared__ unsigned smem[];
    int*   s_tok = (int*)smem;
    float* s_w   = (float*)(smem + 128);

    int e = blockIdx.z;
    int count = g_counts[e];
    int row0 = blockIdx.y * 128;
    if (row0 >= count) return;
    int col0 = blockIdx.x * 128;

    int t = threadIdx.x;
    if (t < 128) {
        int gr = row0 + t;
        int idx = gr < count ? gr : count - 1;
        s_tok[t] = g_tokidx[e * CAP + idx];
        s_w[t]   = (gr < count) ? g_tokw[e * CAP + idx] : 0.0f;
    }
    __syncthreads();

    int lane = t & 31, wid = t >> 5;
    int warp_m = wid >> 2, warp_n = wid & 3;
    int gid = lane >> 2, tig = lane & 3;
    int lrow = (lane & 7) + (lane & 8);
    int lk   = ((lane >> 4) & 1) * 8;

    uint32_t sb = smem_u32(smem);

    const unsigned* he  = g_hh + ((size_t)e * CAP + row0) * (D_FF / 2);
    const unsigned* w2e = g_w2h + (size_t)e * (D_FF * D_MODEL / 2) + col0 / 2;

    const unsigned* aS[4]; uint32_t aD[4];
    const unsigned* bS[4]; uint32_t bD[4];
#pragma unroll
    for (int i = 0; i < 4; i++) {
        int cid = t + 256 * i;
        int arow = cid >> 3, ach = cid & 7;
        aS[i] = he + (size_t)arow * (D_FF / 2) + ach * 4;
        aD[i] = sb + OFFA(0) + arow * APITCH + ach * 16;
        int brow = cid >> 4, bch = cid & 15;
        bS[i] = w2e + (size_t)brow * (D_MODEL / 2) + bch * 4;
        bD[i] = sb + OFFB(0) + brow * BPITCH + bch * 16;
    }

    float acc[4][4][4];
#pragma unroll
    for (int i = 0; i < 4; i++)
#pragma unroll
        for (int j = 0; j < 4; j++)
#pragma unroll
            for (int q = 0; q < 4; q++) acc[i][j][q] = 0.0f;

#pragma unroll
    for (int i = 0; i < 4; i++) { cp16(aD[i], aS[i]); cp16(bD[i], bS[i]); }
    CP_COMMIT();

    const int NIT = D_FF / BK;   // 64
    int buf = 0;
    for (int it = 0; it < NIT; it++) {
        CP_WAIT0();
        __syncthreads();
        if (it + 1 < NIT) {
            int ktw = (it + 1) * (BK / 2);
            uint32_t as = (buf ^ 1) * ABYTES;
            uint32_t bs = (buf ^ 1) * BBYTES;
#pragma unroll
            for (int i = 0; i < 4; i++) {
                cp16(aD[i] + as, aS[i] + ktw);
                cp16(bD[i] + bs, bS[i] + (size_t)(it + 1) * BK * (D_MODEL / 2));
            }
            CP_COMMIT();
        }

        uint32_t sbA = sb + OFFA(buf);
        uint32_t sbB = sb + OFFB(buf);
#pragma unroll
        for (int ks = 0; ks < BK; ks += 16) {
            unsigned af[4][4], bf[4][2];
#pragma unroll
            for (int i = 0; i < 4; i++) {
                int m = warp_m * 64 + i * 16;
                uint32_t ad = sbA + (m + lrow) * APITCH + (ks + lk) * 2;
                LDMX4(af[i][0], af[i][1], af[i][2], af[i][3], ad);
            }
#pragma unroll
            for (int jj = 0; jj < 2; jj++) {
                uint32_t bd = sbB + (ks + lrow) * BPITCH
                            + (warp_n * 32 + jj * 16 + lk) * 2;
                LDMX4T(bf[jj*2][0], bf[jj*2][1], bf[jj*2+1][0], bf[jj*2+1][1], bd);
            }
#pragma unroll
            for (int i = 0; i < 4; i++)
#pragma unroll
                for (int j = 0; j < 4; j++)
                    mma_f16(acc[i][j], af[i][0], af[i][1], af[i][2], af[i][3],
                            bf[j][0], bf[j][1]);
        }
        buf ^= 1;
    }

    // epilogue: weighted atomic scatter
#pragma unroll
    for (int i = 0; i < 4; i++) {
        int mrow = warp_m * 64 + i * 16 + gid;
#pragma unroll
        for (int half = 0; half < 2; half++) {
            int r = mrow + half * 8;
            int gr = row0 + r;
            if (gr >= count) continue;
            int tok = s_tok[r];
            float w  = s_w[r];
            float* orow = out + (size_t)tok * D_MODEL + col0;
#pragma unroll
            for (int j = 0; j < 4; j++) {
                int c = warp_n * 32 + j * 8 + tig * 2;
                float v0 = acc[i][j][half * 2 + 0] + b2[e * D_MODEL + col0 + c];
                float v1 = acc[i][j][half * 2 + 1] + b2[e * D_MODEL + col0 + c + 1];
                atomicAdd(&orow[c],     w * v0);
                atomicAdd(&orow[c + 1], w * v1);
            }
        }
    }
}

// ---------------- aux loss ----------------
__global__ void aux_kernel(float* out_aux, float invT) {
    if (threadIdx.x == 0 && blockIdx.x == 0) {
        float m[NE]; float mu = 0.0f;
#pragma unroll
        for (int e = 0; e < NE; e++) { m[e] = g_sumprobs[e] * invT; mu += m[e]; }
        mu *= (1.0f / NE);
        float v = 0.0f;
#pragma unroll
        for (int e = 0; e < NE; e++) { float d = m[e] - mu; v += d * d; }
        *out_aux = v / (NE - 1);
    }
}

// ---------------- launch ----------------
extern "C" void kernel_launch(void* const* d_in, const int* in_sizes, int n_in,
                              void* d_out, int out_size) {
    const float* x  = (const float*)d_in[0];
    const float* rw = (const float*)d_in[1];
    const float* rb = (const float*)d_in[2];
    const float* w1 = (const float*)d_in[3];
    const float* b1 = (const float*)d_in[4];
    const float* w2 = (const float*)d_in[5];
    const float* b2 = (const float*)d_in[6];
    float* out = (float*)d_out;

    int T = in_sizes[0] / D_MODEL;

    cudaFuncSetAttribute(ffn1_kernel, cudaFuncAttributeMaxDynamicSharedMemorySize, DYN_BYTES);
    cudaFuncSetAttribute(ffn2_kernel, cudaFuncAttributeMaxDynamicSharedMemorySize, DYN_BYTES);

    cudaMemsetAsync(d_out, 0, (size_t)T * D_MODEL * sizeof(float));
    zero_small_kernel<<<1, 32>>>();
    router_kernel<<<(T + 3) / 4, 128>>>(x, rw, rb, T);

    convx_kernel<<<2048, 256>>>(x, (size_t)T * D_MODEL / 4);
    convw1_kernel<<<8192, 256>>>(w1, (size_t)NE * D_MODEL * D_FF / 4);
    convw2_kernel<<<8192, 256>>>(w2, (size_t)NE * D_FF * D_MODEL / 4);

    dim3 g1(D_FF / 128, CAP / 128, NE);
    ffn1_kernel<<<g1, 256, DYN_BYTES>>>(b1);

    dim3 g2(D_MODEL / 128, CAP / 128, NE);
    ffn2_kernel<<<g2, 256, DYN_BYTES>>>(b2, out);

    if (out_size > T * D_MODEL) {
        aux_kernel<<<1, 32>>>(out + (size_t)T * D_MODEL, 1.0f / (float)T);
    }
}